// round 5
// baseline (speedup 1.0000x reference)
#include <cuda_runtime.h>
#include <cuda_fp16.h>
#include <math.h>

#define N_S 100000
#define N_I 100000
#define NTOT 200000
#define E_EDGES 3200000
#define D 16
#define H 32
#define CHUNK 1024
#define NCHUNK 196   // ceil((NTOT+1)/1024)

// ---------------- scratch (device globals) ----------------
// unified node id space: served = [0,N_S), interfered = [N_S, NTOT)
// messages stored as raw fp16 bits (POD ushort avoids class-type device globals)
__device__ __align__(16) unsigned short g_M[NTOT * H];
__device__ __align__(16) float g_A[NTOT * H];     // aggregation (fp32)
__device__ __align__(16) float g_x[NTOT * D];     // node features (in-place per layer)
__device__ int   g_cnt[NTOT];
__device__ int   g_off[NTOT + 1];
__device__ int   g_cur[NTOT];
__device__ int   g_bsum[NCHUNK];
__device__ int   g_boff[NCHUNK];
__device__ int   g_csr[2 * E_EDGES];
__device__ __align__(16) float g_bfm[N_S * D];
__device__ float g_ss[16];

__device__ __forceinline__ float lrelu(float x) { return fmaxf(x, 0.01f * x); }

__device__ __forceinline__ unsigned short f2h_bits(float x)
{
    return __half_as_ushort(__float2half(x));
}

// ---------------- CSR build ----------------
__global__ void zero_kernel()
{
    int i = blockIdx.x * blockDim.x + threadIdx.x;
    int n = gridDim.x * blockDim.x;
    for (int k = i; k < NTOT; k += n) g_cnt[k] = 0;
    if (i < 16) g_ss[i] = 0.f;
}

__global__ void hist_kernel(const int* __restrict__ ei_si, const int* __restrict__ ei_is)
{
    int i = blockIdx.x * blockDim.x + threadIdx.x;
    int n = gridDim.x * blockDim.x;
    for (int e = i; e < E_EDGES; e += n) {
        atomicAdd(&g_cnt[N_S + ei_si[E_EDGES + e]], 1);  // dst interfered
        atomicAdd(&g_cnt[ei_is[E_EDGES + e]], 1);        // dst served
    }
}

__global__ void scan1_kernel()
{
    __shared__ int sh[CHUNK];
    int t = threadIdx.x;
    int i = blockIdx.x * CHUNK + t;
    sh[t] = (i < NTOT) ? g_cnt[i] : 0;
    __syncthreads();
    for (int o = CHUNK / 2; o > 0; o >>= 1) {
        if (t < o) sh[t] += sh[t + o];
        __syncthreads();
    }
    if (t == 0) g_bsum[blockIdx.x] = sh[0];
}

__global__ void scan2_kernel()
{
    __shared__ int sh[256];
    int t = threadIdx.x;
    int v = (t < NCHUNK) ? g_bsum[t] : 0;
    sh[t] = v;
    __syncthreads();
    for (int o = 1; o < 256; o <<= 1) {
        int u = (t >= o) ? sh[t - o] : 0;
        __syncthreads();
        sh[t] += u;
        __syncthreads();
    }
    if (t < NCHUNK) g_boff[t] = sh[t] - v;   // exclusive
}

__global__ void scan3_kernel()
{
    __shared__ int sh[CHUNK];
    int t = threadIdx.x;
    int i = blockIdx.x * CHUNK + t;
    int v = (i < NTOT) ? g_cnt[i] : 0;
    sh[t] = v;
    __syncthreads();
    for (int o = 1; o < CHUNK; o <<= 1) {
        int u = (t >= o) ? sh[t - o] : 0;
        __syncthreads();
        sh[t] += u;
        __syncthreads();
    }
    if (i <= NTOT) {
        int off = g_boff[blockIdx.x] + sh[t] - v;   // exclusive prefix
        g_off[i] = off;
        if (i < NTOT) g_cur[i] = off;
    }
}

__global__ void fill_kernel(const int* __restrict__ ei_si, const int* __restrict__ ei_is)
{
    int i = blockIdx.x * blockDim.x + threadIdx.x;
    int n = gridDim.x * blockDim.x;
    for (int e = i; e < E_EDGES; e += n) {
        {   // relation si: src served, dst interfered
            int dst = N_S + ei_si[E_EDGES + e];
            int src = ei_si[e];
            g_csr[atomicAdd(&g_cur[dst], 1)] = src;
        }
        {   // relation is: src interfered, dst served
            int dst = ei_is[E_EDGES + e];
            int src = N_S + ei_is[e];
            g_csr[atomicAdd(&g_cur[dst], 1)] = src;
        }
    }
}

// ---------------- msg MLP from external inputs (thread-per-node) ----------------
__global__ void __launch_bounds__(256) msg0_kernel(
    const float* __restrict__ xs_ext, const float* __restrict__ xi_ext,
    const float* __restrict__ Wm1, const float* __restrict__ bm1,
    const float* __restrict__ Wm2, const float* __restrict__ bm2)
{
    __shared__ __align__(16) float sW1t[32 * 16];   // Wm1 transposed [j][k]
    __shared__ __align__(16) float sW2t[32 * 32];
    __shared__ float sb1[32], sb2[32];
    __shared__ float sm[256 * 33];                   // staging, padded

    int t = threadIdx.x;
    for (int i = t; i < 16 * 32; i += 256) { int k = i >> 5, j = i & 31; sW1t[j * 16 + k] = Wm1[i]; }
    for (int i = t; i < 32 * 32; i += 256) { int k = i >> 5, j = i & 31; sW2t[j * 32 + k] = Wm2[i]; }
    if (t < 32) { sb1[t] = bm1[t]; sb2[t] = bm2[t]; }
    __syncthreads();

    int base = blockIdx.x * 256;
    int node = base + t;
    if (node < NTOT) {
        const float* xp = (node < N_S) ? (xs_ext + node * D) : (xi_ext + (node - N_S) * D);
        float x[16];
        #pragma unroll
        for (int i = 0; i < 4; i++) {
            float4 v = ((const float4*)xp)[i];
            x[4*i] = v.x; x[4*i+1] = v.y; x[4*i+2] = v.z; x[4*i+3] = v.w;
        }
        float h[32];
        #pragma unroll
        for (int j = 0; j < 32; j++) {
            float acc = sb1[j];
            #pragma unroll
            for (int k = 0; k < 16; k += 4) {
                float4 w = *(const float4*)&sW1t[j * 16 + k];
                acc += x[k]*w.x + x[k+1]*w.y + x[k+2]*w.z + x[k+3]*w.w;
            }
            h[j] = lrelu(acc);
        }
        #pragma unroll
        for (int j = 0; j < 32; j++) {
            float acc = sb2[j];
            #pragma unroll
            for (int k = 0; k < 32; k += 4) {
                float4 w = *(const float4*)&sW2t[j * 32 + k];
                acc += h[k]*w.x + h[k+1]*w.y + h[k+2]*w.z + h[k+3]*w.w;
            }
            sm[t * 33 + j] = lrelu(acc);
        }
    }
    __syncthreads();
    int nvalid = min(256, NTOT - base);
    for (int i = t; i < nvalid * H; i += 256) {
        int n = i >> 5, j = i & 31;
        g_M[base * H + i] = f2h_bits(sm[n * 33 + j]);
    }
}

// ---------------- gather aggregation (warp per dst, CSR, fp16 messages) --------
// 4 lanes per edge (one uint4 = 8 halves each), 8 edges in flight per warp.
__global__ void gather_kernel()
{
    int gtid = blockIdx.x * blockDim.x + threadIdx.x;
    int warpId = gtid >> 5;
    int nwarps = (gridDim.x * blockDim.x) >> 5;
    int lane = threadIdx.x & 31;
    int v = lane & 3;        // uint4 slot within 64B row
    int sub = lane >> 2;     // edge sub-slot (8 edges in flight)

    const uint4* Mv = (const uint4*)g_M;

    for (int d = warpId; d < NTOT; d += nwarps) {
        int beg = g_off[d];
        int end = g_off[d + 1];
        float acc[8];
        #pragma unroll
        for (int i = 0; i < 8; i++) acc[i] = 0.f;

        for (int it = beg + sub; it < end; it += 8) {
            int src = g_csr[it];
            uint4 m = Mv[src * 4 + v];
            unsigned int w[4] = {m.x, m.y, m.z, m.w};
            #pragma unroll
            for (int i = 0; i < 4; i++) {
                float2 f = __half22float2(*(const __half2*)&w[i]);
                acc[2*i]   += f.x;
                acc[2*i+1] += f.y;
            }
        }
        // reduce the 8 sub-slots (lanes differing in bits 2,3,4)
        #pragma unroll
        for (int o = 4; o <= 16; o <<= 1) {
            #pragma unroll
            for (int i = 0; i < 8; i++)
                acc[i] += __shfl_xor_sync(0xffffffffu, acc[i], o);
        }
        if (sub == 0) {
            float4* out = (float4*)(g_A + d * H + v * 8);
            out[0] = make_float4(acc[0], acc[1], acc[2], acc[3]);
            out[1] = make_float4(acc[4], acc[5], acc[6], acc[7]);
        }
    }
}

// ---------------- fused update MLP + next-layer msg MLP (thread-per-node) -------
// 128 threads/block keeps total static smem at ~40 KB (< 48 KB hard limit).
__global__ void __launch_bounds__(128) upd_kernel(
    const float* __restrict__ xs_ext, const float* __restrict__ xi_ext,
    const float* __restrict__ Wu1, const float* __restrict__ bu1,
    const float* __restrict__ Wu2, const float* __restrict__ bu2,
    const float* __restrict__ Wm1, const float* __restrict__ bm1,
    const float* __restrict__ Wm2, const float* __restrict__ bm2,
    int layer)
{
    __shared__ __align__(16) float sWu1t[32 * 48];
    __shared__ __align__(16) float sWu2t[16 * 32];
    __shared__ __align__(16) float sW1t[32 * 16];
    __shared__ __align__(16) float sW2t[32 * 32];
    __shared__ float sbu1[32], sbu2[16], sb1[32], sb2[32];
    __shared__ float smM[128 * 33];
    __shared__ float smX[128 * 17];

    int t = threadIdx.x;
    for (int i = t; i < 48 * 32; i += 128) { int k = i >> 5, j = i & 31; sWu1t[j * 48 + k] = Wu1[i]; }
    for (int i = t; i < 32 * 16; i += 128) { int k = i >> 4, j = i & 15; sWu2t[j * 32 + k] = Wu2[i]; }
    for (int i = t; i < 16 * 32; i += 128) { int k = i >> 5, j = i & 31; sW1t[j * 16 + k] = Wm1[i]; }
    for (int i = t; i < 32 * 32; i += 128) { int k = i >> 5, j = i & 31; sW2t[j * 32 + k] = Wm2[i]; }
    if (t < 32) { sbu1[t] = bu1[t]; sb1[t] = bm1[t]; sb2[t] = bm2[t]; }
    if (t < 16) { sbu2[t] = bu2[t]; }
    __syncthreads();

    int base = blockIdx.x * 128;
    int node = base + t;
    if (node < NTOT) {
        float in[48];
        const float* xp = (layer == 0)
            ? ((node < N_S) ? (xs_ext + node * D) : (xi_ext + (node - N_S) * D))
            : (g_x + node * D);
        #pragma unroll
        for (int i = 0; i < 4; i++) {
            float4 vv = ((const float4*)xp)[i];
            in[4*i] = vv.x; in[4*i+1] = vv.y; in[4*i+2] = vv.z; in[4*i+3] = vv.w;
        }
        const float4* ap = (const float4*)(g_A + node * H);
        #pragma unroll
        for (int i = 0; i < 8; i++) {
            float4 vv = ap[i];
            in[16+4*i] = vv.x; in[17+4*i] = vv.y; in[18+4*i] = vv.z; in[19+4*i] = vv.w;
        }
        float h[32];
        #pragma unroll
        for (int j = 0; j < 32; j++) {
            float acc = sbu1[j];
            #pragma unroll
            for (int k = 0; k < 48; k += 4) {
                float4 w = *(const float4*)&sWu1t[j * 48 + k];
                acc += in[k]*w.x + in[k+1]*w.y + in[k+2]*w.z + in[k+3]*w.w;
            }
            h[j] = lrelu(acc);
        }
        float o[16];
        #pragma unroll
        for (int j = 0; j < 16; j++) {
            float acc = sbu2[j];
            #pragma unroll
            for (int k = 0; k < 32; k += 4) {
                float4 w = *(const float4*)&sWu2t[j * 32 + k];
                acc += h[k]*w.x + h[k+1]*w.y + h[k+2]*w.z + h[k+3]*w.w;
            }
            o[j] = lrelu(acc);
            smX[t * 17 + j] = o[j];
        }
        if (layer < 2) {
            float h2[32];
            #pragma unroll
            for (int j = 0; j < 32; j++) {
                float acc = sb1[j];
                #pragma unroll
                for (int k = 0; k < 16; k += 4) {
                    float4 w = *(const float4*)&sW1t[j * 16 + k];
                    acc += o[k]*w.x + o[k+1]*w.y + o[k+2]*w.z + o[k+3]*w.w;
                }
                h2[j] = lrelu(acc);
            }
            #pragma unroll
            for (int j = 0; j < 32; j++) {
                float acc = sb2[j];
                #pragma unroll
                for (int k = 0; k < 32; k += 4) {
                    float4 w = *(const float4*)&sW2t[j * 32 + k];
                    acc += h2[k]*w.x + h2[k+1]*w.y + h2[k+2]*w.z + h2[k+3]*w.w;
                }
                smM[t * 33 + j] = lrelu(acc);
            }
        }
    }
    __syncthreads();
    int nvalid = min(128, NTOT - base);
    for (int i = t; i < nvalid * D; i += 128) {
        int n = i >> 4, j = i & 15;
        g_x[base * D + i] = smX[n * 17 + j];
    }
    if (layer < 2) {
        for (int i = t; i < nvalid * H; i += 128) {
            int n = i >> 5, j = i & 31;
            g_M[base * H + i] = f2h_bits(smM[n * 33 + j]);
        }
    }
}

// ---------------- final: bfm = tanh(x_s @ Wo + bo), column sum-of-squares -------
__global__ void __launch_bounds__(256) final_kernel(const float* __restrict__ Wo,
                                                    const float* __restrict__ bo)
{
    __shared__ __align__(16) float sWot[16 * 16];
    __shared__ float sbo[16];
    __shared__ float ssum[16];

    int t = threadIdx.x;
    if (t < 256) { int k = t >> 4, j = t & 15; sWot[j * 16 + k] = Wo[t]; }
    if (t < 16) { sbo[t] = bo[t]; ssum[t] = 0.f; }
    __syncthreads();

    float sq[16];
    #pragma unroll
    for (int j = 0; j < 16; j++) sq[j] = 0.f;

    int gtid = blockIdx.x * blockDim.x + t;
    int n = gridDim.x * blockDim.x;
    for (int node = gtid; node < N_S; node += n) {
        float x[16];
        #pragma unroll
        for (int i = 0; i < 4; i++) {
            float4 v = ((const float4*)(g_x + node * D))[i];
            x[4*i] = v.x; x[4*i+1] = v.y; x[4*i+2] = v.z; x[4*i+3] = v.w;
        }
        float y[16];
        #pragma unroll
        for (int j = 0; j < 16; j++) {
            float acc = sbo[j];
            #pragma unroll
            for (int k = 0; k < 16; k += 4) {
                float4 w = *(const float4*)&sWot[j * 16 + k];
                acc += x[k]*w.x + x[k+1]*w.y + x[k+2]*w.z + x[k+3]*w.w;
            }
            y[j] = tanhf(acc);
            sq[j] += y[j] * y[j];
        }
        float4* op = (float4*)(g_bfm + node * D);
        #pragma unroll
        for (int i = 0; i < 4; i++)
            op[i] = make_float4(y[4*i], y[4*i+1], y[4*i+2], y[4*i+3]);
    }

    #pragma unroll
    for (int o = 16; o > 0; o >>= 1) {
        #pragma unroll
        for (int j = 0; j < 16; j++)
            sq[j] += __shfl_xor_sync(0xffffffffu, sq[j], o);
    }
    if ((t & 31) == 0) {
        #pragma unroll
        for (int j = 0; j < 16; j++) atomicAdd(&ssum[j], sq[j]);
    }
    __syncthreads();
    if (t < 16) atomicAdd(&g_ss[t], ssum[t]);
}

// ---------------- out: compute scales from g_ss in-block, apply, write ---------
__global__ void out_kernel(float* __restrict__ out)
{
    __shared__ float sscale[16];
    int t = threadIdx.x;
    if (t < 16) {
        int c = t & 7;
        float nrm = sqrtf(g_ss[c] + g_ss[c + 8]);
        sscale[t] = (nrm > 1.0f) ? (1.0f / nrm) : 1.0f;
    }
    __syncthreads();

    int gtid = blockIdx.x * blockDim.x + t;
    int n = gridDim.x * blockDim.x;
    const int Q = (N_S * D) / 4;
    const float4* bfm4 = (const float4*)g_bfm;
    const float4* sc4 = (const float4*)sscale;
    float4* out4 = (float4*)out;
    for (int i = gtid; i < Q; i += n) {
        float4 s = sc4[i & 3];
        float4 b = bfm4[i];
        b.x *= s.x; b.y *= s.y; b.z *= s.z; b.w *= s.w;
        out4[i] = b;
    }
}

// ---------------- launch --------------------------------------------------------
extern "C" void kernel_launch(void* const* d_in, const int* in_sizes, int n_in,
                              void* d_out, int out_size)
{
    const float* xs  = (const float*)d_in[0];
    const float* xi  = (const float*)d_in[1];
    const int* ei_si = (const int*)d_in[2];
    const int* ei_is = (const int*)d_in[3];
    const float* Wm1 = (const float*)d_in[4];
    const float* bm1 = (const float*)d_in[5];
    const float* Wm2 = (const float*)d_in[6];
    const float* bm2 = (const float*)d_in[7];
    const float* Wu1 = (const float*)d_in[8];
    const float* bu1 = (const float*)d_in[9];
    const float* Wu2 = (const float*)d_in[10];
    const float* bu2 = (const float*)d_in[11];
    const float* Wo  = (const float*)d_in[12];
    const float* bo  = (const float*)d_in[13];

    // CSR build (amortized over 3 layers, 2 relations)
    zero_kernel<<<256, 256>>>();
    hist_kernel<<<1184, 256>>>(ei_si, ei_is);
    scan1_kernel<<<NCHUNK, CHUNK>>>();
    scan2_kernel<<<1, 256>>>();
    scan3_kernel<<<NCHUNK, CHUNK>>>();
    fill_kernel<<<1184, 256>>>(ei_si, ei_is);

    msg0_kernel<<<(NTOT + 255) / 256, 256>>>(xs, xi, Wm1, bm1, Wm2, bm2);

    for (int l = 0; l < 3; l++) {
        gather_kernel<<<1184, 256>>>();
        upd_kernel<<<(NTOT + 127) / 128, 128>>>(xs, xi, Wu1, bu1, Wu2, bu2,
                                                Wm1, bm1, Wm2, bm2, l);
    }

    final_kernel<<<391, 256>>>(Wo, bo);
    out_kernel<<<256, 256>>>((float*)d_out);
}